// round 13
// baseline (speedup 1.0000x reference)
#include <cuda_runtime.h>
#include <math_constants.h>

#define EMBED    512
#define MAXLEN   2048
#define B2       256
#define TILE     64                // tokens per energy CTA
#define NTILES   (MAXLEN / TILE)   // 32
#define ETHREADS 512
#define EWARPS   (ETHREADS / 32)   // 16
#define PBLK     128               // prep CTAs
#define PD       (EMBED / PBLK)    // 4 output dims per prep CTA

// Folded linear direction: v = W^T * weight_vec.
// (Bias term dropped: softmax is shift-invariant, softmax(x.v + c) == softmax(x.v).)
__device__ float g_v[EMBED];
__device__ float g_energy[B2 * MAXLEN];   // holds exp(x.v); 2 MB, L2-resident

// ---------------------------------------------------------------------------
// Prep (single pass, 128 CTAs): CTA blk owns dims d0..d0+3. Thread t handles
// e=t with one float4 load; warp shuffles + smem tree reduce 4 components.
// Triggers PDL completion for the energy kernel.
// ---------------------------------------------------------------------------
__global__ __launch_bounds__(EMBED)
void prep_kernel(const float* __restrict__ W,
                 const float* __restrict__ wv) {
    __shared__ float sp[16][PD];

    const int t    = threadIdx.x;    // e index
    const int warp = t >> 5;
    const int lane = t & 31;
    const int d0   = blockIdx.x * PD;

    const float w = wv[t];
    const float4 w0 = *(const float4*)(W + (size_t)t * EMBED + d0);

    float a[PD];
    a[0] = w0.x * w; a[1] = w0.y * w; a[2] = w0.z * w; a[3] = w0.w * w;

    #pragma unroll
    for (int off = 16; off > 0; off >>= 1) {
        #pragma unroll
        for (int j = 0; j < PD; ++j)
            a[j] += __shfl_xor_sync(0xffffffffu, a[j], off);
    }
    if (lane == 0) {
        #pragma unroll
        for (int j = 0; j < PD; ++j) sp[warp][j] = a[j];
    }
    __syncthreads();

    if (t < PD) {
        float s = 0.0f;
        #pragma unroll
        for (int wdx = 0; wdx < 16; ++wdx) s += sp[wdx][t];
        g_v[d0 + t] = s;
    }
#if __CUDA_ARCH__ >= 900
    cudaTriggerProgrammaticLaunchCompletion();
#endif
}

// ---------------------------------------------------------------------------
// Energies: grid (NTILES, B2), 64-token tiles. Stores exp(x.v) directly
// (bounded energies, idle MUFU pipe). PDL secondary: first 2 tokens
// prefetched before cudaGridDependencySynchronize.
// ---------------------------------------------------------------------------
__global__ __launch_bounds__(ETHREADS)
void energy_kernel(const float* __restrict__ q,
                   const int*   __restrict__ lens) {
    const int b   = blockIdx.y;
    const int len = __ldg(lens + b);
    const int l0  = blockIdx.x * TILE;
    if (l0 >= len) return;                // empty tile: zero DRAM traffic

    const int tid  = threadIdx.x;
    const int warp = tid >> 5;
    const int lane = tid & 31;

    const float4* __restrict__ qrow =
        (const float4*)(q + (size_t)b * MAXLEN * EMBED);
    const int end = min(l0 + TILE, len);

    // ---- prefetch first pair of tokens (independent of prep's output) ----
    const int l  = l0 + warp;
    const int lB = l + EWARPS;
    const bool hasA = (l  < end);
    const bool hasB = (lB < end);
    float4 a0[4], a1[4];
    if (hasA) {
        const float4* __restrict__ qp = qrow + (size_t)l * (EMBED / 4);
        #pragma unroll
        for (int k = 0; k < 4; ++k) a0[k] = __ldcs(qp + lane + 32 * k);
    }
    if (hasB) {
        const float4* __restrict__ qp = qrow + (size_t)lB * (EMBED / 4);
        #pragma unroll
        for (int k = 0; k < 4; ++k) a1[k] = __ldcs(qp + lane + 32 * k);
    }

#if __CUDA_ARCH__ >= 900
    cudaGridDependencySynchronize();      // wait for prep results
#endif

    float4 vv[4];
    const float4* __restrict__ gv4 = (const float4*)g_v;
    #pragma unroll
    for (int k = 0; k < 4; ++k) vv[k] = gv4[lane + 32 * k];

    float* __restrict__ erow = g_energy + (size_t)b * MAXLEN;

    // ---- first (prefetched) iteration ----
    {
        float s0 = 0.0f, s1 = 0.0f;
        if (hasA) {
            #pragma unroll
            for (int k = 0; k < 4; ++k)
                s0 += a0[k].x * vv[k].x + a0[k].y * vv[k].y
                    + a0[k].z * vv[k].z + a0[k].w * vv[k].w;
        }
        if (hasB) {
            #pragma unroll
            for (int k = 0; k < 4; ++k)
                s1 += a1[k].x * vv[k].x + a1[k].y * vv[k].y
                    + a1[k].z * vv[k].z + a1[k].w * vv[k].w;
        }
        #pragma unroll
        for (int off = 16; off > 0; off >>= 1) {
            s0 += __shfl_xor_sync(0xffffffffu, s0, off);
            s1 += __shfl_xor_sync(0xffffffffu, s1, off);
        }
        if (lane == 0) {
            if (hasA) erow[l]  = __expf(s0);
            if (hasB) erow[lB] = __expf(s1);
        }
    }

    // ---- remaining iterations (partial tiles) ----
    for (int ll = l + 2 * EWARPS; ll < end; ll += 2 * EWARPS) {
        const int  ll2  = ll + EWARPS;
        const bool has2 = (ll2 < end);
        const float4* __restrict__ qp0 = qrow + (size_t)ll  * (EMBED / 4);
        const float4* __restrict__ qp1 = qrow + (size_t)ll2 * (EMBED / 4);

        float4 b0[4], b1[4];
        #pragma unroll
        for (int k = 0; k < 4; ++k) b0[k] = __ldcs(qp0 + lane + 32 * k);
        if (has2) {
            #pragma unroll
            for (int k = 0; k < 4; ++k) b1[k] = __ldcs(qp1 + lane + 32 * k);
        }

        float s0 = 0.0f, s1 = 0.0f;
        #pragma unroll
        for (int k = 0; k < 4; ++k)
            s0 += b0[k].x * vv[k].x + b0[k].y * vv[k].y
                + b0[k].z * vv[k].z + b0[k].w * vv[k].w;
        if (has2) {
            #pragma unroll
            for (int k = 0; k < 4; ++k)
                s1 += b1[k].x * vv[k].x + b1[k].y * vv[k].y
                    + b1[k].z * vv[k].z + b1[k].w * vv[k].w;
        }

        #pragma unroll
        for (int off = 16; off > 0; off >>= 1) {
            s0 += __shfl_xor_sync(0xffffffffu, s0, off);
            s1 += __shfl_xor_sync(0xffffffffu, s1, off);
        }
        if (lane == 0) {
            erow[ll] = __expf(s0);
            if (has2) erow[ll2] = __expf(s1);
        }
    }
}

// ---------------------------------------------------------------------------
// Normalize: one CTA (512 threads) per row. g_energy already holds exp;
// one block sum + scale + streaming store. PDL secondary behind energy.
// ---------------------------------------------------------------------------
#define STHREADS 512
#define SWARPS   (STHREADS / 32)   // 16
__global__ __launch_bounds__(STHREADS)
void softmax_kernel(const int* __restrict__ lens,
                    float*     __restrict__ out) {
    __shared__ float sred[SWARPS];

    const int b    = blockIdx.x;
    const int tid  = threadIdx.x;
    const int warp = tid >> 5;
    const int lane = tid & 31;
    const int base = tid * 4;
    const int len  = __ldg(lens + b);     // independent of energy results

#if __CUDA_ARCH__ >= 900
    cudaGridDependencySynchronize();      // wait for energy grid
#endif

    const float4* __restrict__ erow4 =
        (const float4*)(g_energy + (size_t)b * MAXLEN);

    float4 e = erow4[tid];                // exp values, masked comps stale
    e.x = (base + 0 < len) ? e.x : 0.0f;
    e.y = (base + 1 < len) ? e.y : 0.0f;
    e.z = (base + 2 < len) ? e.z : 0.0f;
    e.w = (base + 3 < len) ? e.w : 0.0f;

    float ssum = e.x + e.y + e.z + e.w;
    #pragma unroll
    for (int off = 16; off > 0; off >>= 1)
        ssum += __shfl_xor_sync(0xffffffffu, ssum, off);
    if (lane == 0) sred[warp] = ssum;
    __syncthreads();
    {
        float t = sred[lane & (SWARPS - 1)];
        #pragma unroll
        for (int off = 8; off > 0; off >>= 1)
            t += __shfl_xor_sync(0xffffffffu, t, off);
        ssum = t;
    }
    const float inv = 1.0f / ssum;

    float4 o;
    o.x = e.x * inv; o.y = e.y * inv; o.z = e.z * inv; o.w = e.w * inv;
    __stcs((float4*)(out + (size_t)b * MAXLEN) + tid, o);
}

// ---------------------------------------------------------------------------
// Launch with PDL chaining: prep -> energy -> normalize.
// inputs: questions, questions_lens, lin_w, lin_b, weight_vec
// ---------------------------------------------------------------------------
extern "C" void kernel_launch(void* const* d_in, const int* in_sizes, int n_in,
                              void* d_out, int out_size) {
    const float* questions = (const float*)d_in[0];
    const int*   lens      = (const int*)  d_in[1];
    const float* lin_w     = (const float*)d_in[2];
    const float* wv        = (const float*)d_in[4];
    float* out = (float*)d_out;

    prep_kernel<<<PBLK, EMBED>>>(lin_w, wv);

    cudaLaunchAttribute pdl[1];
    pdl[0].id = cudaLaunchAttributeProgrammaticStreamSerialization;
    pdl[0].val.programmaticStreamSerializationAllowed = 1;

    {
        cudaLaunchConfig_t cfg = {};
        cfg.gridDim  = dim3(NTILES, B2, 1);
        cfg.blockDim = dim3(ETHREADS, 1, 1);
        cfg.stream   = 0;
        cfg.attrs    = pdl;
        cfg.numAttrs = 1;
        cudaLaunchKernelEx(&cfg, energy_kernel, questions, lens);
    }
    {
        cudaLaunchConfig_t cfg = {};
        cfg.gridDim  = dim3(B2, 1, 1);
        cfg.blockDim = dim3(STHREADS, 1, 1);
        cfg.stream   = 0;
        cfg.attrs    = pdl;
        cfg.numAttrs = 1;
        cudaLaunchKernelEx(&cfg, softmax_kernel, lens, out);
    }
}

// round 14
// speedup vs baseline: 1.0012x; 1.0012x over previous
#include <cuda_runtime.h>
#include <math_constants.h>

#define EMBED    512
#define MAXLEN   2048
#define B2       256
#define TILE     64                // tokens per energy CTA
#define NTILES   (MAXLEN / TILE)   // 32
#define ETHREADS 512
#define EWARPS   (ETHREADS / 32)   // 16
#define PBLK     128               // prep CTAs
#define PD       (EMBED / PBLK)    // 4 output dims per prep CTA

// Folded linear direction: v = W^T * weight_vec.
// (Bias dropped: softmax is shift-invariant.)
__device__ float g_v[EMBED];
__device__ float g_energy[B2 * MAXLEN];   // holds exp(x.v); 2 MB, L2-resident

// ---------------------------------------------------------------------------
// Prep (single pass, 128 CTAs): CTA blk owns dims d0..d0+3. Thread t handles
// e=t with one float4 load; warp shuffles + smem tree reduce 4 components.
// Triggers PDL completion for the energy kernel.
// ---------------------------------------------------------------------------
__global__ __launch_bounds__(EMBED)
void prep_kernel(const float* __restrict__ W,
                 const float* __restrict__ wv) {
    __shared__ float sp[16][PD];

    const int t    = threadIdx.x;    // e index
    const int warp = t >> 5;
    const int lane = t & 31;
    const int d0   = blockIdx.x * PD;

    const float w = wv[t];
    const float4 w0 = *(const float4*)(W + (size_t)t * EMBED + d0);

    float a[PD];
    a[0] = w0.x * w; a[1] = w0.y * w; a[2] = w0.z * w; a[3] = w0.w * w;

    #pragma unroll
    for (int off = 16; off > 0; off >>= 1) {
        #pragma unroll
        for (int j = 0; j < PD; ++j)
            a[j] += __shfl_xor_sync(0xffffffffu, a[j], off);
    }
    if (lane == 0) {
        #pragma unroll
        for (int j = 0; j < PD; ++j) sp[warp][j] = a[j];
    }
    __syncthreads();

    if (t < PD) {
        float s = 0.0f;
        #pragma unroll
        for (int wdx = 0; wdx < 16; ++wdx) s += sp[wdx][t];
        g_v[d0 + t] = s;
    }
#if __CUDA_ARCH__ >= 900
    cudaTriggerProgrammaticLaunchCompletion();
#endif
}

// ---------------------------------------------------------------------------
// Energies: grid (NTILES, B2), 64-token tiles. Stores exp(x.v) directly
// (bounded energies, idle MUFU pipe). PDL secondary behind the tiny prep:
// first 2 tokens prefetched before cudaGridDependencySynchronize.
// ---------------------------------------------------------------------------
__global__ __launch_bounds__(ETHREADS)
void energy_kernel(const float* __restrict__ q,
                   const int*   __restrict__ lens) {
    const int b   = blockIdx.y;
    const int len = __ldg(lens + b);
    const int l0  = blockIdx.x * TILE;
    if (l0 >= len) return;                // empty tile: zero DRAM traffic

    const int tid  = threadIdx.x;
    const int warp = tid >> 5;
    const int lane = tid & 31;

    const float4* __restrict__ qrow =
        (const float4*)(q + (size_t)b * MAXLEN * EMBED);
    const int end = min(l0 + TILE, len);

    // ---- prefetch first pair of tokens (independent of prep's output) ----
    const int l  = l0 + warp;
    const int lB = l + EWARPS;
    const bool hasA = (l  < end);
    const bool hasB = (lB < end);
    float4 a0[4], a1[4];
    if (hasA) {
        const float4* __restrict__ qp = qrow + (size_t)l * (EMBED / 4);
        #pragma unroll
        for (int k = 0; k < 4; ++k) a0[k] = __ldcs(qp + lane + 32 * k);
    }
    if (hasB) {
        const float4* __restrict__ qp = qrow + (size_t)lB * (EMBED / 4);
        #pragma unroll
        for (int k = 0; k < 4; ++k) a1[k] = __ldcs(qp + lane + 32 * k);
    }

#if __CUDA_ARCH__ >= 900
    cudaGridDependencySynchronize();      // wait for prep results
#endif

    float4 vv[4];
    const float4* __restrict__ gv4 = (const float4*)g_v;
    #pragma unroll
    for (int k = 0; k < 4; ++k) vv[k] = gv4[lane + 32 * k];

    float* __restrict__ erow = g_energy + (size_t)b * MAXLEN;

    // ---- first (prefetched) iteration ----
    {
        float s0 = 0.0f, s1 = 0.0f;
        if (hasA) {
            #pragma unroll
            for (int k = 0; k < 4; ++k)
                s0 += a0[k].x * vv[k].x + a0[k].y * vv[k].y
                    + a0[k].z * vv[k].z + a0[k].w * vv[k].w;
        }
        if (hasB) {
            #pragma unroll
            for (int k = 0; k < 4; ++k)
                s1 += a1[k].x * vv[k].x + a1[k].y * vv[k].y
                    + a1[k].z * vv[k].z + a1[k].w * vv[k].w;
        }
        #pragma unroll
        for (int off = 16; off > 0; off >>= 1) {
            s0 += __shfl_xor_sync(0xffffffffu, s0, off);
            s1 += __shfl_xor_sync(0xffffffffu, s1, off);
        }
        if (lane == 0) {
            if (hasA) erow[l]  = __expf(s0);
            if (hasB) erow[lB] = __expf(s1);
        }
    }

    // ---- remaining iterations (partial tiles) ----
    for (int ll = l + 2 * EWARPS; ll < end; ll += 2 * EWARPS) {
        const int  ll2  = ll + EWARPS;
        const bool has2 = (ll2 < end);
        const float4* __restrict__ qp0 = qrow + (size_t)ll  * (EMBED / 4);
        const float4* __restrict__ qp1 = qrow + (size_t)ll2 * (EMBED / 4);

        float4 b0[4], b1[4];
        #pragma unroll
        for (int k = 0; k < 4; ++k) b0[k] = __ldcs(qp0 + lane + 32 * k);
        if (has2) {
            #pragma unroll
            for (int k = 0; k < 4; ++k) b1[k] = __ldcs(qp1 + lane + 32 * k);
        }

        float s0 = 0.0f, s1 = 0.0f;
        #pragma unroll
        for (int k = 0; k < 4; ++k)
            s0 += b0[k].x * vv[k].x + b0[k].y * vv[k].y
                + b0[k].z * vv[k].z + b0[k].w * vv[k].w;
        if (has2) {
            #pragma unroll
            for (int k = 0; k < 4; ++k)
                s1 += b1[k].x * vv[k].x + b1[k].y * vv[k].y
                    + b1[k].z * vv[k].z + b1[k].w * vv[k].w;
        }

        #pragma unroll
        for (int off = 16; off > 0; off >>= 1) {
            s0 += __shfl_xor_sync(0xffffffffu, s0, off);
            s1 += __shfl_xor_sync(0xffffffffu, s1, off);
        }
        if (lane == 0) {
            erow[ll] = __expf(s0);
            if (has2) erow[ll2] = __expf(s1);
        }
    }
}

// ---------------------------------------------------------------------------
// Normalize: one CTA (512 threads) per row. g_energy already holds exp;
// one block sum + scale + streaming store. PLAIN launch (no PDL): launching
// it as a PDL secondary would let its 256x512 CTAs occupy SM slots and spin
// during the energy kernel's tail waves.
// ---------------------------------------------------------------------------
#define STHREADS 512
#define SWARPS   (STHREADS / 32)   // 16
__global__ __launch_bounds__(STHREADS)
void softmax_kernel(const int* __restrict__ lens,
                    float*     __restrict__ out) {
    __shared__ float sred[SWARPS];

    const int b    = blockIdx.x;
    const int tid  = threadIdx.x;
    const int warp = tid >> 5;
    const int lane = tid & 31;
    const int base = tid * 4;
    const int len  = __ldg(lens + b);

    const float4* __restrict__ erow4 =
        (const float4*)(g_energy + (size_t)b * MAXLEN);

    float4 e = erow4[tid];                // exp values, masked comps stale
    e.x = (base + 0 < len) ? e.x : 0.0f;
    e.y = (base + 1 < len) ? e.y : 0.0f;
    e.z = (base + 2 < len) ? e.z : 0.0f;
    e.w = (base + 3 < len) ? e.w : 0.0f;

    float ssum = e.x + e.y + e.z + e.w;
    #pragma unroll
    for (int off = 16; off > 0; off >>= 1)
        ssum += __shfl_xor_sync(0xffffffffu, ssum, off);
    if (lane == 0) sred[warp] = ssum;
    __syncthreads();
    {
        float t = sred[lane & (SWARPS - 1)];
        #pragma unroll
        for (int off = 8; off > 0; off >>= 1)
            t += __shfl_xor_sync(0xffffffffu, t, off);
        ssum = t;
    }
    const float inv = 1.0f / ssum;

    float4 o;
    o.x = e.x * inv; o.y = e.y * inv; o.z = e.z * inv; o.w = e.w * inv;
    __stcs((float4*)(out + (size_t)b * MAXLEN) + tid, o);
}

// ---------------------------------------------------------------------------
// Launch: prep -> (PDL) energy -> (plain) normalize.
// inputs: questions, questions_lens, lin_w, lin_b, weight_vec
// ---------------------------------------------------------------------------
extern "C" void kernel_launch(void* const* d_in, const int* in_sizes, int n_in,
                              void* d_out, int out_size) {
    const float* questions = (const float*)d_in[0];
    const int*   lens      = (const int*)  d_in[1];
    const float* lin_w     = (const float*)d_in[2];
    const float* wv        = (const float*)d_in[4];
    float* out = (float*)d_out;

    prep_kernel<<<PBLK, EMBED>>>(lin_w, wv);

    cudaLaunchAttribute pdl[1];
    pdl[0].id = cudaLaunchAttributeProgrammaticStreamSerialization;
    pdl[0].val.programmaticStreamSerializationAllowed = 1;

    {
        cudaLaunchConfig_t cfg = {};
        cfg.gridDim  = dim3(NTILES, B2, 1);
        cfg.blockDim = dim3(ETHREADS, 1, 1);
        cfg.stream   = 0;
        cfg.attrs    = pdl;
        cfg.numAttrs = 1;
        cudaLaunchKernelEx(&cfg, energy_kernel, questions, lens);
    }

    softmax_kernel<<<B2, STHREADS>>>(lens, out);
}

// round 15
// speedup vs baseline: 1.0066x; 1.0055x over previous
#include <cuda_runtime.h>
#include <math_constants.h>

#define EMBED    512
#define MAXLEN   2048
#define B2       256
#define BHALF    (B2 / 2)          // 128 rows per branch
#define TILE     64                // tokens per energy CTA
#define NTILES   (MAXLEN / TILE)   // 32
#define ETHREADS 512
#define EWARPS   (ETHREADS / 32)   // 16
#define PBLK     128               // prep CTAs
#define PD       (EMBED / PBLK)    // 4 output dims per prep CTA

// Folded linear direction: v = W^T * weight_vec.
// (Bias dropped: softmax is shift-invariant.)
__device__ float g_v[EMBED];
__device__ float g_energy[B2 * MAXLEN];   // holds exp(x.v); 2 MB, L2-resident

// ---------------------------------------------------------------------------
// Prep (single pass, 128 CTAs): CTA blk owns dims d0..d0+3. Thread t handles
// e=t with one float4 load; warp shuffles + smem tree reduce 4 components.
// Triggers PDL completion for the energy kernel.
// ---------------------------------------------------------------------------
__global__ __launch_bounds__(EMBED)
void prep_kernel(const float* __restrict__ W,
                 const float* __restrict__ wv) {
    __shared__ float sp[16][PD];

    const int t    = threadIdx.x;    // e index
    const int warp = t >> 5;
    const int lane = t & 31;
    const int d0   = blockIdx.x * PD;

    const float w = wv[t];
    const float4 w0 = *(const float4*)(W + (size_t)t * EMBED + d0);

    float a[PD];
    a[0] = w0.x * w; a[1] = w0.y * w; a[2] = w0.z * w; a[3] = w0.w * w;

    #pragma unroll
    for (int off = 16; off > 0; off >>= 1) {
        #pragma unroll
        for (int j = 0; j < PD; ++j)
            a[j] += __shfl_xor_sync(0xffffffffu, a[j], off);
    }
    if (lane == 0) {
        #pragma unroll
        for (int j = 0; j < PD; ++j) sp[warp][j] = a[j];
    }
    __syncthreads();

    if (t < PD) {
        float s = 0.0f;
        #pragma unroll
        for (int wdx = 0; wdx < 16; ++wdx) s += sp[wdx][t];
        g_v[d0 + t] = s;
    }
#if __CUDA_ARCH__ >= 900
    cudaTriggerProgrammaticLaunchCompletion();
#endif
}

// ---------------------------------------------------------------------------
// Energies for rows [b_off, b_off+BHALF): grid (NTILES, BHALF).
// Stores exp(x.v) directly (bounded energies, idle MUFU pipe). On s0 this is
// a PDL secondary behind prep (prefetch before gridsync); on s1 the gridsync
// resolves immediately (deps satisfied at launch via the fork event).
// ---------------------------------------------------------------------------
__global__ __launch_bounds__(ETHREADS)
void energy_kernel(const float* __restrict__ q,
                   const int*   __restrict__ lens,
                   int b_off) {
    const int b   = b_off + blockIdx.y;
    const int len = __ldg(lens + b);
    const int l0  = blockIdx.x * TILE;
    if (l0 >= len) return;                // empty tile: zero DRAM traffic

    const int tid  = threadIdx.x;
    const int warp = tid >> 5;
    const int lane = tid & 31;

    const float4* __restrict__ qrow =
        (const float4*)(q + (size_t)b * MAXLEN * EMBED);
    const int end = min(l0 + TILE, len);

    // ---- prefetch first pair of tokens (independent of prep's output) ----
    const int l  = l0 + warp;
    const int lB = l + EWARPS;
    const bool hasA = (l  < end);
    const bool hasB = (lB < end);
    float4 a0[4], a1[4];
    if (hasA) {
        const float4* __restrict__ qp = qrow + (size_t)l * (EMBED / 4);
        #pragma unroll
        for (int k = 0; k < 4; ++k) a0[k] = __ldcs(qp + lane + 32 * k);
    }
    if (hasB) {
        const float4* __restrict__ qp = qrow + (size_t)lB * (EMBED / 4);
        #pragma unroll
        for (int k = 0; k < 4; ++k) a1[k] = __ldcs(qp + lane + 32 * k);
    }

#if __CUDA_ARCH__ >= 900
    cudaGridDependencySynchronize();      // wait for prep results (s0 branch)
#endif

    float4 vv[4];
    const float4* __restrict__ gv4 = (const float4*)g_v;
    #pragma unroll
    for (int k = 0; k < 4; ++k) vv[k] = gv4[lane + 32 * k];

    float* __restrict__ erow = g_energy + (size_t)b * MAXLEN;

    // ---- first (prefetched) iteration ----
    {
        float s0 = 0.0f, s1 = 0.0f;
        if (hasA) {
            #pragma unroll
            for (int k = 0; k < 4; ++k)
                s0 += a0[k].x * vv[k].x + a0[k].y * vv[k].y
                    + a0[k].z * vv[k].z + a0[k].w * vv[k].w;
        }
        if (hasB) {
            #pragma unroll
            for (int k = 0; k < 4; ++k)
                s1 += a1[k].x * vv[k].x + a1[k].y * vv[k].y
                    + a1[k].z * vv[k].z + a1[k].w * vv[k].w;
        }
        #pragma unroll
        for (int off = 16; off > 0; off >>= 1) {
            s0 += __shfl_xor_sync(0xffffffffu, s0, off);
            s1 += __shfl_xor_sync(0xffffffffu, s1, off);
        }
        if (lane == 0) {
            if (hasA) erow[l]  = __expf(s0);
            if (hasB) erow[lB] = __expf(s1);
        }
    }

    // ---- remaining iterations (partial tiles) ----
    for (int ll = l + 2 * EWARPS; ll < end; ll += 2 * EWARPS) {
        const int  ll2  = ll + EWARPS;
        const bool has2 = (ll2 < end);
        const float4* __restrict__ qp0 = qrow + (size_t)ll  * (EMBED / 4);
        const float4* __restrict__ qp1 = qrow + (size_t)ll2 * (EMBED / 4);

        float4 b0[4], b1[4];
        #pragma unroll
        for (int k = 0; k < 4; ++k) b0[k] = __ldcs(qp0 + lane + 32 * k);
        if (has2) {
            #pragma unroll
            for (int k = 0; k < 4; ++k) b1[k] = __ldcs(qp1 + lane + 32 * k);
        }

        float s0 = 0.0f, s1 = 0.0f;
        #pragma unroll
        for (int k = 0; k < 4; ++k)
            s0 += b0[k].x * vv[k].x + b0[k].y * vv[k].y
                + b0[k].z * vv[k].z + b0[k].w * vv[k].w;
        if (has2) {
            #pragma unroll
            for (int k = 0; k < 4; ++k)
                s1 += b1[k].x * vv[k].x + b1[k].y * vv[k].y
                    + b1[k].z * vv[k].z + b1[k].w * vv[k].w;
        }

        #pragma unroll
        for (int off = 16; off > 0; off >>= 1) {
            s0 += __shfl_xor_sync(0xffffffffu, s0, off);
            s1 += __shfl_xor_sync(0xffffffffu, s1, off);
        }
        if (lane == 0) {
            erow[ll] = __expf(s0);
            if (has2) erow[ll2] = __expf(s1);
        }
    }
}

// ---------------------------------------------------------------------------
// Normalize rows [b_off, b_off+BHALF): one CTA (512 threads) per row.
// g_energy already holds exp; one block sum + scale + streaming store.
// ---------------------------------------------------------------------------
#define STHREADS 512
#define SWARPS   (STHREADS / 32)   // 16
__global__ __launch_bounds__(STHREADS)
void softmax_kernel(const int* __restrict__ lens,
                    float*     __restrict__ out,
                    int b_off) {
    __shared__ float sred[SWARPS];

    const int b    = b_off + blockIdx.x;
    const int tid  = threadIdx.x;
    const int warp = tid >> 5;
    const int lane = tid & 31;
    const int base = tid * 4;
    const int len  = __ldg(lens + b);

    const float4* __restrict__ erow4 =
        (const float4*)(g_energy + (size_t)b * MAXLEN);

    float4 e = erow4[tid];                // exp values, masked comps stale
    e.x = (base + 0 < len) ? e.x : 0.0f;
    e.y = (base + 1 < len) ? e.y : 0.0f;
    e.z = (base + 2 < len) ? e.z : 0.0f;
    e.w = (base + 3 < len) ? e.w : 0.0f;

    float ssum = e.x + e.y + e.z + e.w;
    #pragma unroll
    for (int off = 16; off > 0; off >>= 1)
        ssum += __shfl_xor_sync(0xffffffffu, ssum, off);
    if (lane == 0) sred[warp] = ssum;
    __syncthreads();
    {
        float t = sred[lane & (SWARPS - 1)];
        #pragma unroll
        for (int off = 8; off > 0; off >>= 1)
            t += __shfl_xor_sync(0xffffffffu, t, off);
        ssum = t;
    }
    const float inv = 1.0f / ssum;

    float4 o;
    o.x = e.x * inv; o.y = e.y * inv; o.z = e.z * inv; o.w = e.w * inv;
    __stcs((float4*)(out + (size_t)b * MAXLEN) + tid, o);
}

// ---------------------------------------------------------------------------
// Launch: forked two-branch pipeline so softmaxA overlaps energyB's tail.
//   s0: prep -> (PDL) energyA(rows 0..127) -> softmaxA
//   s1: wait(fork) -> energyB(rows 128..255) -> softmaxB -> join
// Stream/events are created once (host-side objects only; no device memory).
// inputs: questions, questions_lens, lin_w, lin_b, weight_vec
// ---------------------------------------------------------------------------
extern "C" void kernel_launch(void* const* d_in, const int* in_sizes, int n_in,
                              void* d_out, int out_size) {
    const float* questions = (const float*)d_in[0];
    const int*   lens      = (const int*)  d_in[1];
    const float* lin_w     = (const float*)d_in[2];
    const float* wv        = (const float*)d_in[4];
    float* out = (float*)d_out;

    static cudaStream_t s1 = [] {
        cudaStream_t s;
        cudaStreamCreateWithFlags(&s, cudaStreamNonBlocking);
        return s;
    }();
    static cudaEvent_t evFork = [] {
        cudaEvent_t e;
        cudaEventCreateWithFlags(&e, cudaEventDisableTiming);
        return e;
    }();
    static cudaEvent_t evJoin = [] {
        cudaEvent_t e;
        cudaEventCreateWithFlags(&e, cudaEventDisableTiming);
        return e;
    }();

    // s0: prep
    prep_kernel<<<PBLK, EMBED>>>(lin_w, wv);

    // fork: s1 starts after prep
    cudaEventRecord(evFork, 0);
    cudaStreamWaitEvent(s1, evFork, 0);

    // s0: energyA as PDL secondary behind prep
    cudaLaunchAttribute pdl[1];
    pdl[0].id = cudaLaunchAttributeProgrammaticStreamSerialization;
    pdl[0].val.programmaticStreamSerializationAllowed = 1;
    {
        cudaLaunchConfig_t cfg = {};
        cfg.gridDim  = dim3(NTILES, BHALF, 1);
        cfg.blockDim = dim3(ETHREADS, 1, 1);
        cfg.stream   = 0;
        cfg.attrs    = pdl;
        cfg.numAttrs = 1;
        cudaLaunchKernelEx(&cfg, energy_kernel, questions, lens, 0);
    }

    // s1: energyB (plain; prep guaranteed done via fork event)
    energy_kernel<<<dim3(NTILES, BHALF, 1), ETHREADS, 0, s1>>>(
        questions, lens, BHALF);

    // s0: softmaxA — runs after energyA, overlapping energyB's tail
    softmax_kernel<<<BHALF, STHREADS>>>(lens, out, 0);

    // s1: softmaxB, then join back to s0
    softmax_kernel<<<BHALF, STHREADS, 0, s1>>>(lens, out, BHALF);
    cudaEventRecord(evJoin, s1);
    cudaStreamWaitEvent(0, evJoin, 0);
}

// round 16
// speedup vs baseline: 1.0102x; 1.0035x over previous
#include <cuda_runtime.h>
#include <math_constants.h>

#define EMBED    512
#define MAXLEN   2048
#define B2       256
#define NCHUNK   4
#define BCHUNK   (B2 / NCHUNK)     // 64 rows per chunk
#define TILE     64                // tokens per energy CTA
#define NTILES   (MAXLEN / TILE)   // 32
#define ETHREADS 512
#define EWARPS   (ETHREADS / 32)   // 16
#define PBLK     128               // prep CTAs
#define PD       (EMBED / PBLK)    // 4 output dims per prep CTA

// Folded linear direction: v = W^T * weight_vec.
// (Bias dropped: softmax is shift-invariant.)
__device__ float g_v[EMBED];
__device__ float g_energy[B2 * MAXLEN];   // holds exp(x.v); 2 MB, L2-resident

// ---------------------------------------------------------------------------
// Prep (single pass, 128 CTAs): CTA blk owns dims d0..d0+3. Thread t handles
// e=t with one float4 load; warp shuffles + smem tree reduce 4 components.
// Triggers PDL completion for the chunk-0 energy kernel.
// ---------------------------------------------------------------------------
__global__ __launch_bounds__(EMBED)
void prep_kernel(const float* __restrict__ W,
                 const float* __restrict__ wv) {
    __shared__ float sp[16][PD];

    const int t    = threadIdx.x;    // e index
    const int warp = t >> 5;
    const int lane = t & 31;
    const int d0   = blockIdx.x * PD;

    const float w = wv[t];
    const float4 w0 = *(const float4*)(W + (size_t)t * EMBED + d0);

    float a[PD];
    a[0] = w0.x * w; a[1] = w0.y * w; a[2] = w0.z * w; a[3] = w0.w * w;

    #pragma unroll
    for (int off = 16; off > 0; off >>= 1) {
        #pragma unroll
        for (int j = 0; j < PD; ++j)
            a[j] += __shfl_xor_sync(0xffffffffu, a[j], off);
    }
    if (lane == 0) {
        #pragma unroll
        for (int j = 0; j < PD; ++j) sp[warp][j] = a[j];
    }
    __syncthreads();

    if (t < PD) {
        float s = 0.0f;
        #pragma unroll
        for (int wdx = 0; wdx < 16; ++wdx) s += sp[wdx][t];
        g_v[d0 + t] = s;
    }
#if __CUDA_ARCH__ >= 900
    cudaTriggerProgrammaticLaunchCompletion();
#endif
}

// ---------------------------------------------------------------------------
// Energies for rows [b_off, b_off+BCHUNK): grid (NTILES, BCHUNK).
// Stores exp(x.v) directly (bounded energies, idle MUFU pipe). Chunk 0 is a
// PDL secondary behind prep (prefetch before gridsync); side-stream chunks
// start after prep's fork event, so their gridsync resolves immediately.
// ---------------------------------------------------------------------------
__global__ __launch_bounds__(ETHREADS)
void energy_kernel(const float* __restrict__ q,
                   const int*   __restrict__ lens,
                   int b_off) {
    const int b   = b_off + blockIdx.y;
    const int len = __ldg(lens + b);
    const int l0  = blockIdx.x * TILE;
    if (l0 >= len) return;                // empty tile: zero DRAM traffic

    const int tid  = threadIdx.x;
    const int warp = tid >> 5;
    const int lane = tid & 31;

    const float4* __restrict__ qrow =
        (const float4*)(q + (size_t)b * MAXLEN * EMBED);
    const int end = min(l0 + TILE, len);

    // ---- prefetch first pair of tokens (independent of prep's output) ----
    const int l  = l0 + warp;
    const int lB = l + EWARPS;
    const bool hasA = (l  < end);
    const bool hasB = (lB < end);
    float4 a0[4], a1[4];
    if (hasA) {
        const float4* __restrict__ qp = qrow + (size_t)l * (EMBED / 4);
        #pragma unroll
        for (int k = 0; k < 4; ++k) a0[k] = __ldcs(qp + lane + 32 * k);
    }
    if (hasB) {
        const float4* __restrict__ qp = qrow + (size_t)lB * (EMBED / 4);
        #pragma unroll
        for (int k = 0; k < 4; ++k) a1[k] = __ldcs(qp + lane + 32 * k);
    }

#if __CUDA_ARCH__ >= 900
    cudaGridDependencySynchronize();      // wait for prep results (chunk 0)
#endif

    float4 vv[4];
    const float4* __restrict__ gv4 = (const float4*)g_v;
    #pragma unroll
    for (int k = 0; k < 4; ++k) vv[k] = gv4[lane + 32 * k];

    float* __restrict__ erow = g_energy + (size_t)b * MAXLEN;

    // ---- first (prefetched) iteration ----
    {
        float s0 = 0.0f, s1 = 0.0f;
        if (hasA) {
            #pragma unroll
            for (int k = 0; k < 4; ++k)
                s0 += a0[k].x * vv[k].x + a0[k].y * vv[k].y
                    + a0[k].z * vv[k].z + a0[k].w * vv[k].w;
        }
        if (hasB) {
            #pragma unroll
            for (int k = 0; k < 4; ++k)
                s1 += a1[k].x * vv[k].x + a1[k].y * vv[k].y
                    + a1[k].z * vv[k].z + a1[k].w * vv[k].w;
        }
        #pragma unroll
        for (int off = 16; off > 0; off >>= 1) {
            s0 += __shfl_xor_sync(0xffffffffu, s0, off);
            s1 += __shfl_xor_sync(0xffffffffu, s1, off);
        }
        if (lane == 0) {
            if (hasA) erow[l]  = __expf(s0);
            if (hasB) erow[lB] = __expf(s1);
        }
    }

    // ---- remaining iterations (partial tiles) ----
    for (int ll = l + 2 * EWARPS; ll < end; ll += 2 * EWARPS) {
        const int  ll2  = ll + EWARPS;
        const bool has2 = (ll2 < end);
        const float4* __restrict__ qp0 = qrow + (size_t)ll  * (EMBED / 4);
        const float4* __restrict__ qp1 = qrow + (size_t)ll2 * (EMBED / 4);

        float4 b0[4], b1[4];
        #pragma unroll
        for (int k = 0; k < 4; ++k) b0[k] = __ldcs(qp0 + lane + 32 * k);
        if (has2) {
            #pragma unroll
            for (int k = 0; k < 4; ++k) b1[k] = __ldcs(qp1 + lane + 32 * k);
        }

        float s0 = 0.0f, s1 = 0.0f;
        #pragma unroll
        for (int k = 0; k < 4; ++k)
            s0 += b0[k].x * vv[k].x + b0[k].y * vv[k].y
                + b0[k].z * vv[k].z + b0[k].w * vv[k].w;
        if (has2) {
            #pragma unroll
            for (int k = 0; k < 4; ++k)
                s1 += b1[k].x * vv[k].x + b1[k].y * vv[k].y
                    + b1[k].z * vv[k].z + b1[k].w * vv[k].w;
        }

        #pragma unroll
        for (int off = 16; off > 0; off >>= 1) {
            s0 += __shfl_xor_sync(0xffffffffu, s0, off);
            s1 += __shfl_xor_sync(0xffffffffu, s1, off);
        }
        if (lane == 0) {
            erow[ll] = __expf(s0);
            if (has2) erow[ll2] = __expf(s1);
        }
    }
}

// ---------------------------------------------------------------------------
// Normalize rows [b_off, b_off+BCHUNK): one CTA (512 threads) per row.
// g_energy already holds exp; one block sum + scale + streaming store.
// ---------------------------------------------------------------------------
#define STHREADS 512
#define SWARPS   (STHREADS / 32)   // 16
__global__ __launch_bounds__(STHREADS)
void softmax_kernel(const int* __restrict__ lens,
                    float*     __restrict__ out,
                    int b_off) {
    __shared__ float sred[SWARPS];

    const int b    = b_off + blockIdx.x;
    const int tid  = threadIdx.x;
    const int warp = tid >> 5;
    const int lane = tid & 31;
    const int base = tid * 4;
    const int len  = __ldg(lens + b);

    const float4* __restrict__ erow4 =
        (const float4*)(g_energy + (size_t)b * MAXLEN);

    float4 e = erow4[tid];                // exp values, masked comps stale
    e.x = (base + 0 < len) ? e.x : 0.0f;
    e.y = (base + 1 < len) ? e.y : 0.0f;
    e.z = (base + 2 < len) ? e.z : 0.0f;
    e.w = (base + 3 < len) ? e.w : 0.0f;

    float ssum = e.x + e.y + e.z + e.w;
    #pragma unroll
    for (int off = 16; off > 0; off >>= 1)
        ssum += __shfl_xor_sync(0xffffffffu, ssum, off);
    if (lane == 0) sred[warp] = ssum;
    __syncthreads();
    {
        float t = sred[lane & (SWARPS - 1)];
        #pragma unroll
        for (int off = 8; off > 0; off >>= 1)
            t += __shfl_xor_sync(0xffffffffu, t, off);
        ssum = t;
    }
    const float inv = 1.0f / ssum;

    float4 o;
    o.x = e.x * inv; o.y = e.y * inv; o.z = e.z * inv; o.w = e.w * inv;
    __stcs((float4*)(out + (size_t)b * MAXLEN) + tid, o);
}

// ---------------------------------------------------------------------------
// Launch: staggered 4-chunk pipeline.
//   default: prep -> (PDL) E0 -> S0
//   s[i]:    wait(prep) -> Ei -> Si -> done-event   (i = 1..3)
// Energy chunks are launched in row order, so the work distributor dispatches
// (and completes) them staggered; each chunk's softmax overlaps later chunks'
// energy streaming. Only S3 is exposed at the end.
// inputs: questions, questions_lens, lin_w, lin_b, weight_vec
// ---------------------------------------------------------------------------
extern "C" void kernel_launch(void* const* d_in, const int* in_sizes, int n_in,
                              void* d_out, int out_size) {
    const float* questions = (const float*)d_in[0];
    const int*   lens      = (const int*)  d_in[1];
    const float* lin_w     = (const float*)d_in[2];
    const float* wv        = (const float*)d_in[4];
    float* out = (float*)d_out;

    static cudaStream_t s[NCHUNK - 1];
    static cudaEvent_t  evFork;
    static cudaEvent_t  evDone[NCHUNK - 1];
    static bool inited = [] {
        for (int i = 0; i < NCHUNK - 1; ++i) {
            cudaStreamCreateWithFlags(&s[i], cudaStreamNonBlocking);
            cudaEventCreateWithFlags(&evDone[i], cudaEventDisableTiming);
        }
        cudaEventCreateWithFlags(&evFork, cudaEventDisableTiming);
        return true;
    }();
    (void)inited;

    // default stream: prep
    prep_kernel<<<PBLK, EMBED>>>(lin_w, wv);

    // fork to side streams
    cudaEventRecord(evFork, 0);
    for (int i = 0; i < NCHUNK - 1; ++i)
        cudaStreamWaitEvent(s[i], evFork, 0);

    // chunk 0 on default stream as PDL secondary behind prep
    cudaLaunchAttribute pdl[1];
    pdl[0].id = cudaLaunchAttributeProgrammaticStreamSerialization;
    pdl[0].val.programmaticStreamSerializationAllowed = 1;
    {
        cudaLaunchConfig_t cfg = {};
        cfg.gridDim  = dim3(NTILES, BCHUNK, 1);
        cfg.blockDim = dim3(ETHREADS, 1, 1);
        cfg.stream   = 0;
        cfg.attrs    = pdl;
        cfg.numAttrs = 1;
        cudaLaunchKernelEx(&cfg, energy_kernel, questions, lens, 0);
    }

    // chunks 1..3 on side streams, launched in row order for staggered drain
    for (int i = 1; i < NCHUNK; ++i)
        energy_kernel<<<dim3(NTILES, BCHUNK, 1), ETHREADS, 0, s[i - 1]>>>(
            questions, lens, i * BCHUNK);

    // per-chunk softmax: chunk 0 on default, others on their streams
    softmax_kernel<<<BCHUNK, STHREADS>>>(lens, out, 0);
    for (int i = 1; i < NCHUNK; ++i) {
        softmax_kernel<<<BCHUNK, STHREADS, 0, s[i - 1]>>>(lens, out,
                                                          i * BCHUNK);
        cudaEventRecord(evDone[i - 1], s[i - 1]);
    }

    // join all side streams back to the default stream
    for (int i = 0; i < NCHUNK - 1; ++i)
        cudaStreamWaitEvent(0, evDone[i], 0);
}